// round 8
// baseline (speedup 1.0000x reference)
#include <cuda_runtime.h>
#include <cuda_bf16.h>
#include <stdint.h>
#include <math.h>

#define S_LEN   2048
#define D_MODEL 1024
#define NHEADS  16
#define DKH     64
#define HALF_WIN 128
#define BQ      64
#define BKC     64
#define BATCH   2
#define MROWS   (BATCH * S_LEN)   // 4096
#define K3      (3 * D_MODEL)     // 3072
#define NQKV    3072

// ---------------- scratch (static device globals; no allocation) -----------
__device__ float g_qkv[MROWS * NQKV];                // fused q|k|v fp32
__device__ float g_ao [MROWS * D_MODEL];
__device__ __nv_bfloat16 g_xa  [MROWS * K3];         // x split [hi|lo|hi]
__device__ __nv_bfloat16 g_aoa [MROWS * K3];         // attn-out split
__device__ __nv_bfloat16 g_wqkv[NQKV * K3];          // [Wq;Wk;Wv] split [hi|hi|lo]
__device__ __nv_bfloat16 g_wo  [D_MODEL * K3];       // Wo split

// ---------------- fp32 -> bf16x3 split conversion ---------------------------
__device__ __forceinline__ void split_row(
    const float* __restrict__ in, __nv_bfloat16* __restrict__ out,
    int r, int c, int modeB)
{
    float4 v = *(const float4*)(in + (size_t)r * D_MODEL + c);
    float f[4] = {v.x, v.y, v.z, v.w};
    __nv_bfloat16 hi[4], lo[4];
    #pragma unroll
    for (int j = 0; j < 4; j++) {
        hi[j] = __float2bfloat16(f[j]);
        lo[j] = __float2bfloat16(f[j] - __bfloat162float(hi[j]));
    }
    __nv_bfloat162 hp0 = __halves2bfloat162(hi[0], hi[1]);
    __nv_bfloat162 hp1 = __halves2bfloat162(hi[2], hi[3]);
    __nv_bfloat162 lp0 = __halves2bfloat162(lo[0], lo[1]);
    __nv_bfloat162 lp1 = __halves2bfloat162(lo[2], lo[3]);
    __nv_bfloat162* o0 = (__nv_bfloat162*)(out + (size_t)r * K3 + c);
    __nv_bfloat162* o1 = (__nv_bfloat162*)(out + (size_t)r * K3 + D_MODEL + c);
    __nv_bfloat162* o2 = (__nv_bfloat162*)(out + (size_t)r * K3 + 2 * D_MODEL + c);
    o0[0] = hp0; o0[1] = hp1;
    if (modeB) { o1[0] = hp0; o1[1] = hp1; o2[0] = lp0; o2[1] = lp1; }
    else       { o1[0] = lp0; o1[1] = lp1; o2[0] = hp0; o2[1] = hp1; }
}

__global__ __launch_bounds__(256) void conv_split(
    const float* __restrict__ in, __nv_bfloat16* __restrict__ out, int modeB)
{
    split_row(in, out, blockIdx.x, threadIdx.x * 4, modeB);
}

__global__ __launch_bounds__(256) void conv_split_w(
    const float* __restrict__ Wq, const float* __restrict__ Wk,
    const float* __restrict__ Wv, const float* __restrict__ Wo,
    __nv_bfloat16* __restrict__ wqkv, __nv_bfloat16* __restrict__ wo)
{
    int w = blockIdx.y;
    const float* src = (w == 0) ? Wq : (w == 1) ? Wk : (w == 2) ? Wv : Wo;
    __nv_bfloat16* dst = (w == 3) ? wo : wqkv + (size_t)w * D_MODEL * K3;
    split_row(src, dst, blockIdx.x, threadIdx.x * 4, 1);
}

// ---------------- mma.sync bf16 GEMM: Y[M,N] = A[M,K3] @ B[N,K3]^T ----------
#define GBM 128
#define GBN 128
#define GBK 64
#define PADK 72
#define STG 3
#define SMEM_GEMM (STG * (GBM + GBN) * PADK * 2)   // 110592 B

__device__ __forceinline__ uint32_t s2u(const void* p) {
    uint32_t a;
    asm("{ .reg .u64 t; cvta.to.shared.u64 t, %1; cvt.u32.u64 %0, t; }"
        : "=r"(a) : "l"(p));
    return a;
}
__device__ __forceinline__ void cp16(uint32_t dst, const void* src) {
    asm volatile("cp.async.cg.shared.global [%0], [%1], 16;" :: "r"(dst), "l"(src));
}
__device__ __forceinline__ void ldmx4(uint32_t& r0, uint32_t& r1, uint32_t& r2,
                                      uint32_t& r3, uint32_t addr) {
    asm volatile("ldmatrix.sync.aligned.m8n8.x4.shared.b16 {%0,%1,%2,%3}, [%4];"
                 : "=r"(r0), "=r"(r1), "=r"(r2), "=r"(r3) : "r"(addr));
}

__global__ __launch_bounds__(256, 2) void gemm_mma(
    const __nv_bfloat16* __restrict__ A,
    const __nv_bfloat16* __restrict__ B,
    float* __restrict__ Y, int N)
{
    extern __shared__ __nv_bfloat16 smem_g[];

    int tid = threadIdx.x;
    int wid = tid >> 5, lane = tid & 31;
    int wm = wid & 1, wn = wid >> 1;
    int bm = blockIdx.y * GBM, bn = blockIdx.x * GBN;
    int g = lane >> 2, tig = lane & 3;

    int lrow = tid >> 3;
    int lch  = tid & 7;

    uint32_t as_base = s2u(smem_g);
    uint32_t bs_base = as_base + STG * GBM * PADK * 2;

    uint32_t a_ld = as_base +
        ((uint32_t)(wm * 64 + (lane & 15)) * PADK + ((lane >> 4) * 8)) * 2;
    uint32_t b_ld = bs_base +
        ((uint32_t)(wn * 32 + ((lane >> 4) * 8) + (lane & 7)) * PADK +
         (((lane >> 3) & 1) * 8)) * 2;

    const int NIT = K3 / GBK;                   // 48
    const uint32_t ASTG = GBM * PADK * 2;
    const uint32_t BSTG = GBN * PADK * 2;

#define LOAD_STAGE(s, k0)                                                     \
    do {                                                                      \
        _Pragma("unroll")                                                     \
        for (int i = 0; i < 4; i++) {                                         \
            int row = lrow + i * 32;                                          \
            cp16(as_base + (uint32_t)(s) * ASTG + (row * PADK + lch * 8) * 2, \
                 A + (size_t)(bm + row) * K3 + (k0) + lch * 8);               \
            cp16(bs_base + (uint32_t)(s) * BSTG + (row * PADK + lch * 8) * 2, \
                 B + (size_t)(bn + row) * K3 + (k0) + lch * 8);               \
        }                                                                     \
    } while (0)

    LOAD_STAGE(0, 0);
    asm volatile("cp.async.commit_group;");
    LOAD_STAGE(1, GBK);
    asm volatile("cp.async.commit_group;");

    float acc[4][4][4];
    #pragma unroll
    for (int i = 0; i < 4; i++)
        #pragma unroll
        for (int j = 0; j < 4; j++)
            #pragma unroll
            for (int t = 0; t < 4; t++) acc[i][j][t] = 0.f;

    int s = 0;
    for (int it = 0; it < NIT; it++) {
        asm volatile("cp.async.wait_group 1;");
        __syncthreads();

        uint32_t a_s = a_ld + s * ASTG;
        uint32_t b_s = b_ld + s * BSTG;

        #pragma unroll
        for (int kk = 0; kk < GBK; kk += 16) {
            uint32_t af[4][4], bf[4][2];
            #pragma unroll
            for (int i = 0; i < 4; i++)
                ldmx4(af[i][0], af[i][1], af[i][2], af[i][3],
                      a_s + (uint32_t)(i * 16 * PADK + kk) * 2);
            #pragma unroll
            for (int jp = 0; jp < 2; jp++)
                ldmx4(bf[2*jp][0], bf[2*jp][1], bf[2*jp+1][0], bf[2*jp+1][1],
                      b_s + (uint32_t)(jp * 16 * PADK + kk) * 2);
            #pragma unroll
            for (int i = 0; i < 4; i++)
                #pragma unroll
                for (int j = 0; j < 4; j++)
                    asm volatile(
                        "mma.sync.aligned.m16n8k16.row.col.f32.bf16.bf16.f32 "
                        "{%0,%1,%2,%3}, {%4,%5,%6,%7}, {%8,%9}, {%0,%1,%2,%3};"
                        : "+f"(acc[i][j][0]), "+f"(acc[i][j][1]),
                          "+f"(acc[i][j][2]), "+f"(acc[i][j][3])
                        : "r"(af[i][0]), "r"(af[i][1]), "r"(af[i][2]), "r"(af[i][3]),
                          "r"(bf[j][0]), "r"(bf[j][1]));
        }

        int s2 = s + 2; if (s2 >= STG) s2 -= STG;
        if (it + 2 < NIT) LOAD_STAGE(s2, (it + 2) * GBK);
        asm volatile("cp.async.commit_group;");
        s = s + 1; if (s >= STG) s = 0;
    }

    #pragma unroll
    for (int i = 0; i < 4; i++) {
        int r = bm + wm * 64 + i * 16 + g;
        #pragma unroll
        for (int j = 0; j < 4; j++) {
            int c = bn + wn * 32 + j * 8 + 2 * tig;
            *(float2*)&Y[(size_t)r * N + c]       = make_float2(acc[i][j][0], acc[i][j][1]);
            *(float2*)&Y[(size_t)(r + 8) * N + c] = make_float2(acc[i][j][2], acc[i][j][3]);
        }
    }
#undef LOAD_STAGE
}

// ---------------- windowed ALiBi flash attention ----------------------------
// All tiles 64x64 floats, 256B rows, XOR-swizzled 16B groups:
//   phys_group = logical_group ^ (row & 15)
// QsT/KsT transposed ([kk][q/key]) -> QK loop = 2 LDS.128 per kk, conflict-free.
// Vs/Ss row-major -> PV loop LDS.128 conflict-free / broadcast.
#define TILE_B 16384
#define OFF_Q  0
#define OFF_K  16384
#define OFF_V  32768
#define OFF_S  49152
#define SMEM_ATTN 65536

__global__ __launch_bounds__(256, 3) void attn_win(
    const float* __restrict__ q, const float* __restrict__ k,
    const float* __restrict__ v, const float* __restrict__ slopes,
    float* __restrict__ o)
{
    extern __shared__ float smf[];
    char* sm = (char*)smf;

    int qt = blockIdx.x, h = blockIdx.y, b = blockIdx.z;
    int q0 = qt * BQ;
    int tid = threadIdx.x;
    int ty = tid >> 4, tx = tid & 15;
    float slope = slopes[h];

    // ---- load Q transposed + swizzled, pre-scaled by 1/8 ----
    #pragma unroll
    for (int i = 0; i < 4; i++) {
        int idx = tid + i * 256;            // 1024 float4 chunks
        int r  = idx >> 4;                  // query row 0..63
        int cq = idx & 15;                  // kk quad
        float4 qv = *(const float4*)(q + ((size_t)b * S_LEN + q0 + r) * NQKV
                                       + h * DKH + 4 * cq);
        float vals[4] = {qv.x * 0.125f, qv.y * 0.125f, qv.z * 0.125f, qv.w * 0.125f};
        #pragma unroll
        for (int t = 0; t < 4; t++) {
            int kk = 4 * cq + t;
            *(float*)(sm + OFF_Q + kk * 256 + (((r >> 2) ^ (kk & 15)) << 4)
                      + (r & 3) * 4) = vals[t];
        }
    }

    float m_r[4], l_r[4];
    #pragma unroll
    for (int i = 0; i < 4; i++) { m_r[i] = -INFINITY; l_r[i] = 0.f; }

    float acc[4][4];
    #pragma unroll
    for (int i = 0; i < 4; i++)
        #pragma unroll
        for (int j = 0; j < 4; j++) acc[i][j] = 0.f;

    int kstart = q0 - HALF_WIN; if (kstart < 0) kstart = 0;
    int kend   = q0 + BQ + HALF_WIN; if (kend > S_LEN) kend = S_LEN;

    for (int kc = kstart; kc < kend; kc += BKC) {
        __syncthreads();   // previous iter done with K/V/S tiles (and Q store on it 1)
        // K: transposed + swizzled
        #pragma unroll
        for (int i = 0; i < 4; i++) {
            int idx = tid + i * 256;
            int r  = idx >> 4;              // key row 0..63
            int cq = idx & 15;
            float4 kv = *(const float4*)(k + ((size_t)b * S_LEN + kc + r) * NQKV
                                           + h * DKH + 4 * cq);
            float vals[4] = {kv.x, kv.y, kv.z, kv.w};
            #pragma unroll
            for (int t = 0; t < 4; t++) {
                int kk = 4 * cq + t;
                *(float*)(sm + OFF_K + kk * 256 + (((r >> 2) ^ (kk & 15)) << 4)
                          + (r & 3) * 4) = vals[t];
            }
        }
        // V: row-major + swizzled (float4 stores)
        #pragma unroll
        for (int i = 0; i < 4; i++) {
            int idx = tid + i * 256;
            int r  = idx >> 4;              // key row
            int cq = idx & 15;              // dk quad
            float4 vv = *(const float4*)(v + ((size_t)b * S_LEN + kc + r) * NQKV
                                           + h * DKH + 4 * cq);
            *(float4*)(sm + OFF_V + r * 256 + ((cq ^ (r & 15)) << 4)) = vv;
        }
        __syncthreads();

        // ---- S = Q @ K^T : 2 LDS.128 per kk, 16 FMA ----
        float sacc[4][4];
        #pragma unroll
        for (int i = 0; i < 4; i++)
            #pragma unroll
            for (int j = 0; j < 4; j++) sacc[i][j] = 0.f;

        #pragma unroll 16
        for (int kk = 0; kk < DKH; kk++) {
            int sw = kk & 15;
            float4 qv = *(const float4*)(sm + OFF_Q + kk * 256 + ((ty ^ sw) << 4));
            float4 kv = *(const float4*)(sm + OFF_K + kk * 256 + ((tx ^ sw) << 4));
            sacc[0][0] += qv.x*kv.x; sacc[0][1] += qv.x*kv.y; sacc[0][2] += qv.x*kv.z; sacc[0][3] += qv.x*kv.w;
            sacc[1][0] += qv.y*kv.x; sacc[1][1] += qv.y*kv.y; sacc[1][2] += qv.y*kv.z; sacc[1][3] += qv.y*kv.w;
            sacc[2][0] += qv.z*kv.x; sacc[2][1] += qv.z*kv.y; sacc[2][2] += qv.z*kv.z; sacc[2][3] += qv.z*kv.w;
            sacc[3][0] += qv.w*kv.x; sacc[3][1] += qv.w*kv.y; sacc[3][2] += qv.w*kv.z; sacc[3][3] += qv.w*kv.w;
        }

        // bias + mask
        #pragma unroll
        for (int i = 0; i < 4; i++) {
            int qp = q0 + 4*ty + i;
            #pragma unroll
            for (int j = 0; j < 4; j++) {
                int kp = kc + 4*tx + j;
                int d = qp - kp;
                float sv = sacc[i][j] + slope * (float)d;
                if (d > HALF_WIN || d < -HALF_WIN) sv = -INFINITY;
                sacc[i][j] = sv;
            }
        }

        // shuffle softmax over 16 lanes sharing ty
        #pragma unroll
        for (int i = 0; i < 4; i++) {
            float mx = fmaxf(fmaxf(sacc[i][0], sacc[i][1]),
                             fmaxf(sacc[i][2], sacc[i][3]));
            #pragma unroll
            for (int off = 8; off >= 1; off >>= 1)
                mx = fmaxf(mx, __shfl_xor_sync(0xffffffffu, mx, off));
            float mnew = fmaxf(m_r[i], mx);

            float alpha, lsum = 0.f;
            float4 p;
            if (mnew == -INFINITY) {
                alpha = 1.f;
                p = make_float4(0.f, 0.f, 0.f, 0.f);
            } else {
                alpha = __expf(m_r[i] - mnew);
                p.x = __expf(sacc[i][0] - mnew);
                p.y = __expf(sacc[i][1] - mnew);
                p.z = __expf(sacc[i][2] - mnew);
                p.w = __expf(sacc[i][3] - mnew);
                lsum = p.x + p.y + p.z + p.w;
            }
            #pragma unroll
            for (int off = 8; off >= 1; off >>= 1)
                lsum += __shfl_xor_sync(0xffffffffu, lsum, off);

            l_r[i] = l_r[i] * alpha + lsum;
            m_r[i] = mnew;
            int row = 4*ty + i;
            *(float4*)(sm + OFF_S + row * 256 + ((tx ^ (row & 15)) << 4)) = p;
            #pragma unroll
            for (int j = 0; j < 4; j++) acc[i][j] *= alpha;
        }
        __syncthreads();

        // ---- O += P @ V : conflict-free / broadcast LDS.128 ----
        #pragma unroll
        for (int kk = 0; kk < BKC; kk += 4) {
            int kq = kk >> 2;
            float4 p[4], vr[4];
            #pragma unroll
            for (int i = 0; i < 4; i++) {
                int row = 4*ty + i;
                p[i] = *(const float4*)(sm + OFF_S + row * 256
                                        + ((kq ^ (row & 15)) << 4));
            }
            #pragma unroll
            for (int t = 0; t < 4; t++) {
                int row = kk + t;
                vr[t] = *(const float4*)(sm + OFF_V + row * 256
                                         + ((tx ^ (row & 15)) << 4));
            }
            #pragma unroll
            for (int i = 0; i < 4; i++) {
                acc[i][0] += p[i].x * vr[0].x + p[i].y * vr[1].x
                           + p[i].z * vr[2].x + p[i].w * vr[3].x;
                acc[i][1] += p[i].x * vr[0].y + p[i].y * vr[1].y
                           + p[i].z * vr[2].y + p[i].w * vr[3].y;
                acc[i][2] += p[i].x * vr[0].z + p[i].y * vr[1].z
                           + p[i].z * vr[2].z + p[i].w * vr[3].z;
                acc[i][3] += p[i].x * vr[0].w + p[i].y * vr[1].w
                           + p[i].z * vr[2].w + p[i].w * vr[3].w;
            }
        }
    }

    #pragma unroll
    for (int i = 0; i < 4; i++) {
        int r = 4*ty + i;
        float inv = 1.f / l_r[i];
        #pragma unroll
        for (int j = 0; j < 4; j++)
            o[((size_t)b * S_LEN + q0 + r) * D_MODEL + h * DKH + 4*tx + j] =
                acc[i][j] * inv;
    }
}

// ---------------------------------------------------------------------------
extern "C" void kernel_launch(void* const* d_in, const int* in_sizes, int n_in,
                              void* d_out, int out_size)
{
    const float* x      = (const float*)d_in[0];
    const float* Wq     = (const float*)d_in[1];
    const float* Wk     = (const float*)d_in[2];
    const float* Wv     = (const float*)d_in[3];
    const float* Wo     = (const float*)d_in[4];
    const float* slopes = (const float*)d_in[5];
    float* out = (float*)d_out;

    float *qkv, *aob;
    __nv_bfloat16 *xa, *aoa, *wqkv, *wo;
    cudaGetSymbolAddress((void**)&qkv,  g_qkv);
    cudaGetSymbolAddress((void**)&aob,  g_ao);
    cudaGetSymbolAddress((void**)&xa,   g_xa);
    cudaGetSymbolAddress((void**)&aoa,  g_aoa);
    cudaGetSymbolAddress((void**)&wqkv, g_wqkv);
    cudaGetSymbolAddress((void**)&wo,   g_wo);

    cudaFuncSetAttribute(gemm_mma, cudaFuncAttributeMaxDynamicSharedMemorySize,
                         SMEM_GEMM);
    cudaFuncSetAttribute(gemm_mma, cudaFuncAttributePreferredSharedMemoryCarveout,
                         100);
    cudaFuncSetAttribute(attn_win, cudaFuncAttributeMaxDynamicSharedMemorySize,
                         SMEM_ATTN);
    cudaFuncSetAttribute(attn_win, cudaFuncAttributePreferredSharedMemoryCarveout,
                         100);

    conv_split<<<MROWS, 256>>>(x, xa, 0);
    conv_split_w<<<dim3(D_MODEL, 4), 256>>>(Wq, Wk, Wv, Wo, wqkv, wo);

    gemm_mma<<<dim3(NQKV / GBN, MROWS / GBM), 256, SMEM_GEMM>>>(xa, wqkv, qkv, NQKV);

    attn_win<<<dim3(S_LEN / BQ, NHEADS, BATCH), 256, SMEM_ATTN>>>(
        qkv, qkv + D_MODEL, qkv + 2 * D_MODEL, slopes, aob);

    conv_split<<<MROWS, 256>>>(aob, aoa, 0);

    gemm_mma<<<dim3(D_MODEL / GBN, MROWS / GBM), 256, SMEM_GEMM>>>(aoa, wo, out, D_MODEL);
}